// round 9
// baseline (speedup 1.0000x reference)
#include <cuda_runtime.h>
#include <cuda_pipeline.h>

#define S  512
#define S2 (S*S)
#define NBATCH 32
#define NBLK_TOTAL 4096u
#define TROWS 67            // halo rows: 64 + 3
#define TCOLS 35            // halo cols: 32 + 3

// Global accumulators (zero at load; finalize resets them each run)
__device__ double g_acc[2] = {0.0, 0.0};         // [0]=sum|cont|, [1]=sum|pois|
__device__ double g_bc4[NBATCH * 4] = {0.0};     // per-batch per-edge signed sums
__device__ unsigned int g_count = 0u;

// Per-thread 8-row strip over packed cells (.x=u, .y=v, .z=p, .w=q)
template<bool INT>
__device__ __forceinline__ void tile_compute(
    const float4 (*__restrict__ sc)[TCOLS],
    int tx, int ty, int i0, int j0, float& accC, float& accP)
{
    const int cc  = tx + 2;          // cell index of column j
    const int lr0 = ty * 8 + 2;
    const int ir0 = i0 + ty * 8;
    const int j   = j0 + tx;

    // ---- rolled state at row lr0 (4 x LDS.128) ----
    float4 a_m2 = sc[lr0][cc-2], a_m1 = sc[lr0][cc-1], a_0 = sc[lr0][cc], a_p1 = sc[lr0][cc+1];
    float u_m2 = a_m2.x, u_m1 = a_m1.x, u_0 = a_0.x, u_p1 = a_p1.x;
    float v_m1 = a_m1.y, v_0 = a_0.y, v_p1 = a_p1.y;
    float p_m1 = a_m1.z, p_0 = a_0.z, p_p1 = a_p1.z;
    float q_m1 = a_m1.w, q_0 = a_0.w, q_p1 = a_p1.w;

    // row lr0-1 (3 x LDS.128) and lr0-2 (.y only)
    float4 n_m1 = sc[lr0-1][cc-1], n_0 = sc[lr0-1][cc], n_p1 = sc[lr0-1][cc+1];
    float uN_0 = n_0.x, uN_m1 = n_m1.x;
    float vN_m1 = n_m1.y, vN_0 = n_0.y, vN_p1 = n_p1.y;
    float p_N = n_0.z;
    float q_N = n_0.w;
    float vNN_0 = sc[lr0-2][cc].y;

    // ---- flux init between rows ir0-1 and ir0 ----
    float prodN  = (0.5f*(vN_0 + vN_p1)) * (0.5f*(uN_0 + u_0));
    float prodNm = (0.5f*(vN_m1 + vN_0)) * (0.5f*(uN_m1 + u_m1));
    float fn_prev   = prodN  - (u_0  - uN_0);
    float fn_prev_m = prodNm - (u_m1 - uN_m1);
    float ga = 0.5f*(vNN_0 + vN_0);
    float gn_prev = ga*ga - (vN_0 - vNN_0);
    // vn_prev = v_new(ir0-1, j)
    float geN1 = prodN  - (vN_p1 - vN_0);
    float geN0 = prodNm - (vN_0  - vN_m1);
    float gaa  = 0.5f*(vN_0 + v_0);
    float gnN1 = gaa*gaa - (v_0 - vN_0);
    float dvdtN = (-(geN1 - geN0) - (gnN1 - gn_prev) - (p_0 - p_N)) * 100.0f;
    float vn_prev = vN_0 + dvdtN * 0.001f;
    if (!INT) { if (ir0 - 1 < 1) vn_prev = vN_0; }
    gn_prev = gnN1;
    float vN_roll = vN_0;

    #pragma unroll
    for (int k = 0; k < 8; k++) {
        const int lr = lr0 + k;
        const int i  = ir0 + k;
        // next-row loads: 4 x LDS.128 cover every needed value
        float4 s_m2 = sc[lr+1][cc-2];
        float4 s_m1 = sc[lr+1][cc-1];
        float4 s_0  = sc[lr+1][cc];
        float4 s_p1 = sc[lr+1][cc+1];
        float uS_m2 = s_m2.x, uS_m1 = s_m1.x, uS_0 = s_0.x, uS_p1 = s_p1.x;
        float vS_m1 = s_m1.y, vS_0 = s_0.y,  vS_p1 = s_p1.y;
        float pS_m1 = s_m1.z, pS_0 = s_0.z,  pS_p1 = s_p1.z;
        float qS_m1 = s_m1.w, qS_0 = s_0.w,  qS_p1 = s_p1.w;

        // horizontal u fluxes (row lr)
        float ea = 0.5f*(u_m2 + u_m1); float fe0m = ea*ea - (u_m1 - u_m2);
        float eb = 0.5f*(u_m1 + u_0);  float fe0  = eb*eb - (u_0  - u_m1);
        float ec = 0.5f*(u_0  + u_p1); float fe1  = ec*ec - (u_p1 - u_0);
        // shared cross products (u-y flux and v-x flux share them)
        float prod  = (0.5f*(v_0  + v_p1)) * (0.5f*(u_0  + uS_0));
        float prodm = (0.5f*(v_m1 + v_0))  * (0.5f*(u_m1 + uS_m1));
        float fn1  = prod  - (uS_0  - u_0);
        float fn1m = prodm - (uS_m1 - u_m1);
        float ge1  = prod  - (v_p1 - v_0);
        float ge0  = prodm - (v_0  - v_m1);
        float gna = 0.5f*(v_0 + vS_0); float gn1 = gna*gna - (vS_0 - v_0);

        float dudt  = (-(fe1 - fe0)  - (fn1  - fn_prev)   - (p_p1 - p_0)) * 100.0f;
        float dudtm = (-(fe0 - fe0m) - (fn1m - fn_prev_m) - (p_0 - p_m1)) * 100.0f;
        float dvdt  = (-(ge1 - ge0)  - (gn1  - gn_prev)   - (pS_0 - p_0)) * 100.0f;

        float un  = u_0  + dudt  * 0.001f;
        float unm = u_m1 + dudtm * 0.001f;
        float vn  = v_0  + dvdt  * 0.001f;
        if (!INT) {
            if (j > 509 || i > 510)     un  = u_0;
            if (j - 1 < 1 || i > 510)   unm = u_m1;
            if (i > 509)                vn  = v_0;
        }

        float cont  = (u_0 - u_m1 + v_0 - vN_roll) * 100.0f;
        float bconv = ((un - unm) + (vn - vn_prev)) * 100000.0f;
        float lap   = 4.0f*(q_0 - p_0) - (q_p1 - p_p1) - (q_m1 - p_m1)
                    - (qS_0 - pS_0) - (q_N - p_N);
        float pois  = fmaf(lap, 10000.0f, bconv);
        if (INT || (i <= 510 && j <= 510)) {
            accC += fabsf(cont);
            accP += fabsf(pois);
        }

        // roll (center -> north BEFORE overwriting center)
        fn_prev = fn1; fn_prev_m = fn1m; gn_prev = gn1; vn_prev = vn;
        q_N = q_0; p_N = p_0; vN_roll = v_0;
        u_m2 = uS_m2; u_m1 = uS_m1; u_0 = uS_0; u_p1 = uS_p1;
        v_m1 = vS_m1; v_0 = vS_0; v_p1 = vS_p1;
        p_m1 = pS_m1; p_0 = pS_0;   p_p1 = pS_p1;
        q_m1 = qS_m1; q_0 = qS_0;   q_p1 = qS_p1;
    }
}

__global__ __launch_bounds__(256, 5) void pil_kernel(const float* __restrict__ gen,
                                                     const float* __restrict__ pn,
                                                     float* __restrict__ out) {
    // packed halo tile: rows i0-2..i0+64, cols j0-2..j0+32 (67x35 cells of float4)
    __shared__ float4 sc[TROWS][TCOLS];
    __shared__ float redC[8], redP[8];
    __shared__ double dred[8];
    __shared__ unsigned int s_ticket;

    const int bx = blockIdx.x, by = blockIdx.y, b = blockIdx.z;
    const int i0 = 1 + by * 64;
    const int j0 = 1 + bx * 32;
    const int tid = threadIdx.x;
    const int tx = tid & 31, ty = tid >> 5;   // ty = warp id, 0..7

    const float* u = gen + (size_t)b * 3 * S2;
    const float* v = u + S2;
    const float* p = v + S2;
    const float* q = pn + (size_t)b * S2;

    const bool interior = (bx >= 1) && (bx <= 14) && (by >= 1) && (by <= 6);

    // ---- load via cp.async: each warp fills its OWN 11 rows (strip + halo).
    //      All copies issued with no register dependency; one wait at the end.
    //      Overlap rows written twice with identical values (benign).
    if (interior) {
        // no clamps needed: gy in [63,449], gx in [31,481]
        int gx1 = j0 - 2 + tx;
        int gx2 = j0 + 30 + tx;                            // cells 32..34 (tx<3)
        const float* ur0 = u + (size_t)(i0 - 2 + ty * 8) * S;
        #pragma unroll
        for (int rl = 0; rl < 11; rl++) {
            const float* ur = ur0 + rl * S;
            int R = ty * 8 + rl;
            float* cell = (float*)&sc[R][tx];
            __pipeline_memcpy_async(cell + 0, ur + gx1,            4);
            __pipeline_memcpy_async(cell + 1, ur + S2 + gx1,       4);
            __pipeline_memcpy_async(cell + 2, ur + 2 * S2 + gx1,   4);
            __pipeline_memcpy_async(cell + 3, q + (ur - u) + gx1,  4);
            if (tx < 3) {
                float* cell2 = (float*)&sc[R][32 + tx];
                __pipeline_memcpy_async(cell2 + 0, ur + gx2,           4);
                __pipeline_memcpy_async(cell2 + 1, ur + S2 + gx2,      4);
                __pipeline_memcpy_async(cell2 + 2, ur + 2 * S2 + gx2,  4);
                __pipeline_memcpy_async(cell2 + 3, q + (ur - u) + gx2, 4);
            }
        }
    } else {
        int gx1 = j0 - 2 + tx;  gx1 = max(0, min(S - 1, gx1));
        int gx2 = j0 + 30 + tx; gx2 = min(S - 1, gx2);     // cells 32..34 (tx<3)
        int Rbase = ty * 8;
        for (int rl = 0; rl < 11; rl++) {
            int R = Rbase + rl;                            // tile row, max 66
            int gy = i0 - 2 + R; gy = max(0, min(S - 1, gy));
            const float* ur = u + gy * S;
            float* cell = (float*)&sc[R][tx];
            __pipeline_memcpy_async(cell + 0, ur + gx1,            4);
            __pipeline_memcpy_async(cell + 1, ur + S2 + gx1,       4);
            __pipeline_memcpy_async(cell + 2, ur + 2 * S2 + gx1,   4);
            __pipeline_memcpy_async(cell + 3, q + gy * S + gx1,    4);
            if (tx < 3) {
                float* cell2 = (float*)&sc[R][32 + tx];
                __pipeline_memcpy_async(cell2 + 0, ur + gx2,           4);
                __pipeline_memcpy_async(cell2 + 1, ur + S2 + gx2,      4);
                __pipeline_memcpy_async(cell2 + 2, ur + 2 * S2 + gx2,  4);
                __pipeline_memcpy_async(cell2 + 3, q + gy * S + gx2,   4);
            }
        }
    }
    __pipeline_commit();
    __pipeline_wait_prior(0);
    __syncwarp();            // make lanes' cp.async writes visible warp-wide

    float accC = 0.0f, accP = 0.0f;
    if (interior) {
        tile_compute<true >(sc, tx, ty, i0, j0, accC, accP);
    } else {
        tile_compute<false>(sc, tx, ty, i0, j0, accC, accP);

        // BC sums read rows owned by other warps -> block-uniform barrier here.
        __syncthreads();

        // ---- boundary-condition edge sums (edge blocks, from packed smem) ----
        float es = 0.0f; int eidx = -1;
        if (tid < 32) {                       // top/bottom: 32 cols
            int jj = j0 + tid, cc = tid + 2;
            if (by == 0) {
                eidx = 0;
                float4 c1 = sc[1][cc], c2 = sc[2][cc];
                if (jj <= 509) es += c1.x + c2.x;           // u rows 0,1
                if (jj <= 510) es += c1.y + c1.z;           // v,p row 0
            } else if (by == 7) {
                eidx = 1;
                float4 c63 = sc[63][cc], c64 = sc[64][cc];
                if (jj <= 509) es += 2.0f - (c63.x + c64.x);  // u rows 510,511
                if (jj <= 510) es += c64.y + c64.z;           // v,p row 511
            }
        } else if (tid < 96) {                // left/right: 64 rows (2 warps)
            int lane = tid - 32;              // 0..63
            int ii = i0 + lane, lrr = lane + 2;
            if (bx == 0) {
                eidx = 2;
                float4 c1 = sc[lrr][1], c2 = sc[lrr][2];
                if (ii <= 509) es += c1.y + c2.y;           // v cols 0,1
                if (ii <= 510) es += c1.x + c1.z;           // u,p col 0
            } else if (bx == 15) {
                eidx = 3;
                float4 c31 = sc[lrr][31], c32 = sc[lrr][32];
                if (ii <= 509) es += c32.y + c31.y;         // v cols 511,510
                if (ii <= 510) es += c32.x + c32.z;         // u,p col 511
            }
        }
        if (eidx >= 0) {                      // warp-uniform per warp
            #pragma unroll
            for (int off = 16; off > 0; off >>= 1)
                es += __shfl_down_sync(0xFFFFFFFFu, es, off);
            if ((tid & 31) == 0)
                atomicAdd(&g_bc4[b * 4 + eidx], (double)es);
        }
    }

    // ---- block reduction of residual sums ----
    #pragma unroll
    for (int off = 16; off > 0; off >>= 1) {
        accC += __shfl_down_sync(0xFFFFFFFFu, accC, off);
        accP += __shfl_down_sync(0xFFFFFFFFu, accP, off);
    }
    if (tx == 0) { redC[ty] = accC; redP[ty] = accP; }
    __syncthreads();
    if (ty == 0) {
        float rc = (tx < 8) ? redC[tx] : 0.0f;
        float rp = (tx < 8) ? redP[tx] : 0.0f;
        #pragma unroll
        for (int off = 4; off > 0; off >>= 1) {
            rc += __shfl_down_sync(0xFFFFFFFFu, rc, off);
            rp += __shfl_down_sync(0xFFFFFFFFu, rp, off);
        }
        if (tx == 0) {
            atomicAdd(&g_acc[0], (double)rc);
            atomicAdd(&g_acc[1], (double)rp);
        }
    }

    // ---- last-block finalize ----
    __threadfence();
    if (tid == 0) s_ticket = atomicAdd(&g_count, 1u);
    __syncthreads();
    if (s_ticket == NBLK_TOTAL - 1u) {
        double mybc = 0.0;
        if (tid < NBATCH * 4)
            mybc = fabs(atomicAdd(&g_bc4[tid], 0.0));
        #pragma unroll
        for (int off = 16; off > 0; off >>= 1)
            mybc += __shfl_down_sync(0xFFFFFFFFu, mybc, off);
        if (tx == 0) dred[ty] = mybc;
        __syncthreads();
        if (tid == 0) {
            double bc = 0.0;
            #pragma unroll
            for (int kk = 0; kk < 8; kk++) bc += dred[kk];
            double C = atomicAdd(&g_acc[0], 0.0);
            double P = atomicAdd(&g_acc[1], 0.0);
            double denom = 32.0 * 510.0 * 510.0;
            out[0] = (float)(0.4 * (C / denom) + 0.2 * bc + (1.0 - 0.4 - 0.2) * (P / denom));
            g_acc[0] = 0.0; g_acc[1] = 0.0;
        }
        if (tid < NBATCH * 4) g_bc4[tid] = 0.0;
        __threadfence();
        __syncthreads();
        if (tid == 0) g_count = 0u;
    }
}

extern "C" void kernel_launch(void* const* d_in, const int* in_sizes, int n_in,
                              void* d_out, int out_size) {
    const float* gen = (const float*)d_in[0];
    const float* pn  = (const float*)d_in[1];
    float* out = (float*)d_out;
    dim3 grid(16, 8, NBATCH);   // 16 x 8 x 32 = 4096 blocks
    pil_kernel<<<grid, 256>>>(gen, pn, out);
}

// round 10
// speedup vs baseline: 1.2709x; 1.2709x over previous
#include <cuda_runtime.h>
#include <cuda_pipeline.h>

#define S  512
#define S2 (S*S)
#define NBATCH 32
#define NBLK_TOTAL 4096u
#define TROWS 67            // halo rows: 64 + 3
#define TCW   40            // smem row width (floats), 16B-aligned window

// Global accumulators (zero at load; finalize resets them each run)
__device__ double g_acc[2] = {0.0, 0.0};         // [0]=sum|cont|, [1]=sum|pois|
__device__ double g_bc4[NBATCH * 4] = {0.0};     // per-batch per-edge signed sums
__device__ unsigned int g_count = 0u;

// Per-thread 8-row strip. Fields: 0=u, 1=v, 2=p, 3=q. smem col c <-> gx = bx*32-4+c.
template<bool INT>
__device__ __forceinline__ void tile_compute(
    const float (*__restrict__ sf)[TROWS][TCW],
    int tx, int ty, int i0, int j0, float& accC, float& accP)
{
    const int lc  = tx + 5;          // smem col of global column j
    const int lr0 = ty * 8 + 2;
    const int ir0 = i0 + ty * 8;
    const int j   = j0 + tx;

    // ---- rolled state at row lr0 ----
    float u_m2 = sf[0][lr0][lc-2], u_m1 = sf[0][lr0][lc-1], u_0 = sf[0][lr0][lc], u_p1 = sf[0][lr0][lc+1];
    float v_m1 = sf[1][lr0][lc-1], v_0 = sf[1][lr0][lc], v_p1 = sf[1][lr0][lc+1];
    float p_m1 = sf[2][lr0][lc-1], p_0 = sf[2][lr0][lc], p_p1 = sf[2][lr0][lc+1];
    float q_m1 = sf[3][lr0][lc-1], q_0 = sf[3][lr0][lc], q_p1 = sf[3][lr0][lc+1];

    float uN_0 = sf[0][lr0-1][lc], uN_m1 = sf[0][lr0-1][lc-1];
    float vN_m1 = sf[1][lr0-1][lc-1], vN_0 = sf[1][lr0-1][lc], vN_p1 = sf[1][lr0-1][lc+1];
    float p_N = sf[2][lr0-1][lc];
    float q_N = sf[3][lr0-1][lc];
    float vNN_0 = sf[1][lr0-2][lc];

    // ---- flux init between rows ir0-1 and ir0 ----
    float prodN  = (0.5f*(vN_0 + vN_p1)) * (0.5f*(uN_0 + u_0));
    float prodNm = (0.5f*(vN_m1 + vN_0)) * (0.5f*(uN_m1 + u_m1));
    float fn_prev   = prodN  - (u_0  - uN_0);
    float fn_prev_m = prodNm - (u_m1 - uN_m1);
    float ga = 0.5f*(vNN_0 + vN_0);
    float gn_prev = ga*ga - (vN_0 - vNN_0);
    float geN1 = prodN  - (vN_p1 - vN_0);
    float geN0 = prodNm - (vN_0  - vN_m1);
    float gaa  = 0.5f*(vN_0 + v_0);
    float gnN1 = gaa*gaa - (v_0 - vN_0);
    float dvdtN = (-(geN1 - geN0) - (gnN1 - gn_prev) - (p_0 - p_N)) * 100.0f;
    float vn_prev = vN_0 + dvdtN * 0.001f;
    if (!INT) { if (ir0 - 1 < 1) vn_prev = vN_0; }
    gn_prev = gnN1;
    float vN_roll = vN_0;

    #pragma unroll
    for (int k = 0; k < 8; k++) {
        const int lr = lr0 + k;
        const int i  = ir0 + k;
        // next-row loads (16 LDS.32)
        float uS_m2 = sf[0][lr+1][lc-2], uS_m1 = sf[0][lr+1][lc-1], uS_0 = sf[0][lr+1][lc], uS_p1 = sf[0][lr+1][lc+1];
        float vS_m1 = sf[1][lr+1][lc-1], vS_0 = sf[1][lr+1][lc], vS_p1 = sf[1][lr+1][lc+1];
        float pS_m1 = sf[2][lr+1][lc-1], pS_0 = sf[2][lr+1][lc], pS_p1 = sf[2][lr+1][lc+1];
        float qS_m1 = sf[3][lr+1][lc-1], qS_0 = sf[3][lr+1][lc], qS_p1 = sf[3][lr+1][lc+1];

        // horizontal u fluxes (row lr)
        float ea = 0.5f*(u_m2 + u_m1); float fe0m = ea*ea - (u_m1 - u_m2);
        float eb = 0.5f*(u_m1 + u_0);  float fe0  = eb*eb - (u_0  - u_m1);
        float ec = 0.5f*(u_0  + u_p1); float fe1  = ec*ec - (u_p1 - u_0);
        // shared cross products
        float prod  = (0.5f*(v_0  + v_p1)) * (0.5f*(u_0  + uS_0));
        float prodm = (0.5f*(v_m1 + v_0))  * (0.5f*(u_m1 + uS_m1));
        float fn1  = prod  - (uS_0  - u_0);
        float fn1m = prodm - (uS_m1 - u_m1);
        float ge1  = prod  - (v_p1 - v_0);
        float ge0  = prodm - (v_0  - v_m1);
        float gna = 0.5f*(v_0 + vS_0); float gn1 = gna*gna - (vS_0 - v_0);

        float dudt  = (-(fe1 - fe0)  - (fn1  - fn_prev)   - (p_p1 - p_0)) * 100.0f;
        float dudtm = (-(fe0 - fe0m) - (fn1m - fn_prev_m) - (p_0 - p_m1)) * 100.0f;
        float dvdt  = (-(ge1 - ge0)  - (gn1  - gn_prev)   - (pS_0 - p_0)) * 100.0f;

        float un  = u_0  + dudt  * 0.001f;
        float unm = u_m1 + dudtm * 0.001f;
        float vn  = v_0  + dvdt  * 0.001f;
        if (!INT) {
            if (j > 509 || i > 510)     un  = u_0;
            if (j - 1 < 1 || i > 510)   unm = u_m1;
            if (i > 509)                vn  = v_0;
        }

        float cont  = (u_0 - u_m1 + v_0 - vN_roll) * 100.0f;
        float bconv = ((un - unm) + (vn - vn_prev)) * 100000.0f;
        float lap   = 4.0f*(q_0 - p_0) - (q_p1 - p_p1) - (q_m1 - p_m1)
                    - (qS_0 - pS_0) - (q_N - p_N);
        float pois  = fmaf(lap, 10000.0f, bconv);
        if (INT || (i <= 510 && j <= 510)) {
            accC += fabsf(cont);
            accP += fabsf(pois);
        }

        // roll (center -> north BEFORE overwriting center)
        fn_prev = fn1; fn_prev_m = fn1m; gn_prev = gn1; vn_prev = vn;
        q_N = q_0; p_N = p_0; vN_roll = v_0;
        u_m2 = uS_m2; u_m1 = uS_m1; u_0 = uS_0; u_p1 = uS_p1;
        v_m1 = vS_m1; v_0 = vS_0; v_p1 = vS_p1;
        p_m1 = pS_m1; p_0 = pS_0;   p_p1 = pS_p1;
        q_m1 = qS_m1; q_0 = qS_0;   q_p1 = qS_p1;
    }
}

__global__ __launch_bounds__(256, 5) void pil_kernel(const float* __restrict__ gen,
                                                     const float* __restrict__ pn,
                                                     float* __restrict__ out) {
    // planar halo tiles: sf[field][row][col], col window gx = bx*32-4 .. bx*32+35
    __shared__ __align__(16) float sf[4][TROWS][TCW];
    __shared__ float redC[8], redP[8];
    __shared__ double dred[8];
    __shared__ unsigned int s_ticket;

    const int bx = blockIdx.x, by = blockIdx.y, b = blockIdx.z;
    const int i0 = 1 + by * 64;
    const int j0 = 1 + bx * 32;
    const int tid = threadIdx.x;
    const int tx = tid & 31, ty = tid >> 5;   // ty = warp id, 0..7

    const float* u = gen + (size_t)b * 3 * S2;
    const float* q = pn + (size_t)b * S2;
    const int colbase = j0 - 5;               // = bx*32 - 4, 16B aligned

    const bool colInt = (bx >= 1) && (bx <= 14);

    // ---- load: each warp fills its OWN 11 rows (strip + halo) of all 4 fields.
    if (colInt) {
        // cp.async 16B segments. Lane f = tx>>3 covers field f, segment s = tx&7;
        // lanes 0..7 additionally cover segments 8..9 (f2 = tx>>1, s2 = 8+(tx&1)).
        const int f1 = tx >> 3, s1 = tx & 7;
        const float* fp1 = (f1 < 3) ? (u + (size_t)f1 * S2) : q;
        const int f2 = tx >> 1, s2 = 8 + (tx & 1);
        const float* fp2 = (f2 < 3) ? (u + (size_t)f2 * S2) : q;
        const bool lo8 = (tx < 8);
        #pragma unroll
        for (int rl = 0; rl < 11; rl++) {
            int R = ty * 8 + rl;
            int gy = i0 - 2 + R; gy = max(0, min(S - 1, gy));
            const int off = gy * S + colbase;
            __pipeline_memcpy_async(&sf[f1][R][s1 * 4], fp1 + off + s1 * 4, 16);
            if (lo8)
                __pipeline_memcpy_async(&sf[f2][R][s2 * 4], fp2 + off + s2 * 4, 16);
        }
        __pipeline_commit();
        __pipeline_wait_prior(0);
        __syncwarp();
    } else {
        // scalar clamped path (bx = 0 or 15)
        const float* v = u + S2;
        const float* p = v + S2;
        int c1 = tx, c2 = 32 + tx;                       // cols; c2 valid for tx<8
        int gx1 = colbase + c1; gx1 = max(0, min(S - 1, gx1));
        int gx2 = colbase + c2; gx2 = max(0, min(S - 1, gx2));
        for (int rl = 0; rl < 11; rl++) {
            int R = ty * 8 + rl;
            int gy = i0 - 2 + R; gy = max(0, min(S - 1, gy));
            const int ro = gy * S;
            sf[0][R][c1] = u[ro + gx1];
            sf[1][R][c1] = v[ro + gx1];
            sf[2][R][c1] = p[ro + gx1];
            sf[3][R][c1] = q[ro + gx1];
            if (tx < 8) {
                sf[0][R][c2] = u[ro + gx2];
                sf[1][R][c2] = v[ro + gx2];
                sf[2][R][c2] = p[ro + gx2];
                sf[3][R][c2] = q[ro + gx2];
            }
        }
        __syncwarp();
    }

    float accC = 0.0f, accP = 0.0f;
    const bool interior = colInt && (by >= 1) && (by <= 6);
    if (interior) {
        tile_compute<true >(sf, tx, ty, i0, j0, accC, accP);
    } else {
        tile_compute<false>(sf, tx, ty, i0, j0, accC, accP);

        // BC sums read rows owned by other warps -> block-uniform barrier here.
        __syncthreads();

        // ---- boundary-condition edge sums (edge blocks, from smem) ----
        float es = 0.0f; int eidx = -1;
        if (tid < 32) {                       // top/bottom: 32 cols
            int jj = j0 + tid, cc = tid + 5;
            if (by == 0) {
                eidx = 0;
                if (jj <= 509) es += sf[0][1][cc] + sf[0][2][cc];   // u rows 0,1
                if (jj <= 510) es += sf[1][1][cc] + sf[2][1][cc];   // v,p row 0
            } else if (by == 7) {
                eidx = 1;
                if (jj <= 509) es += 2.0f - (sf[0][63][cc] + sf[0][64][cc]); // u rows 510,511
                if (jj <= 510) es += sf[1][64][cc] + sf[2][64][cc];          // v,p row 511
            }
        } else if (tid < 96) {                // left/right: 64 rows (2 warps)
            int lane = tid - 32;              // 0..63
            int ii = i0 + lane, lrr = lane + 2;
            if (bx == 0) {                    // gx=0 -> c=4, gx=1 -> c=5
                eidx = 2;
                if (ii <= 509) es += sf[1][lrr][4] + sf[1][lrr][5];
                if (ii <= 510) es += sf[0][lrr][4] + sf[2][lrr][4];
            } else if (bx == 15) {            // gx=510 -> c=34, gx=511 -> c=35
                eidx = 3;
                if (ii <= 509) es += sf[1][lrr][35] + sf[1][lrr][34];
                if (ii <= 510) es += sf[0][lrr][35] + sf[2][lrr][35];
            }
        }
        if (eidx >= 0) {                      // warp-uniform per warp
            #pragma unroll
            for (int off = 16; off > 0; off >>= 1)
                es += __shfl_down_sync(0xFFFFFFFFu, es, off);
            if ((tid & 31) == 0)
                atomicAdd(&g_bc4[b * 4 + eidx], (double)es);
        }
    }

    // ---- block reduction of residual sums ----
    #pragma unroll
    for (int off = 16; off > 0; off >>= 1) {
        accC += __shfl_down_sync(0xFFFFFFFFu, accC, off);
        accP += __shfl_down_sync(0xFFFFFFFFu, accP, off);
    }
    if (tx == 0) { redC[ty] = accC; redP[ty] = accP; }
    __syncthreads();
    if (ty == 0) {
        float rc = (tx < 8) ? redC[tx] : 0.0f;
        float rp = (tx < 8) ? redP[tx] : 0.0f;
        #pragma unroll
        for (int off = 4; off > 0; off >>= 1) {
            rc += __shfl_down_sync(0xFFFFFFFFu, rc, off);
            rp += __shfl_down_sync(0xFFFFFFFFu, rp, off);
        }
        if (tx == 0) {
            atomicAdd(&g_acc[0], (double)rc);
            atomicAdd(&g_acc[1], (double)rp);
        }
    }

    // ---- last-block finalize ----
    __threadfence();
    if (tid == 0) s_ticket = atomicAdd(&g_count, 1u);
    __syncthreads();
    if (s_ticket == NBLK_TOTAL - 1u) {
        double mybc = 0.0;
        if (tid < NBATCH * 4)
            mybc = fabs(atomicAdd(&g_bc4[tid], 0.0));
        #pragma unroll
        for (int off = 16; off > 0; off >>= 1)
            mybc += __shfl_down_sync(0xFFFFFFFFu, mybc, off);
        if (tx == 0) dred[ty] = mybc;
        __syncthreads();
        if (tid == 0) {
            double bc = 0.0;
            #pragma unroll
            for (int kk = 0; kk < 8; kk++) bc += dred[kk];
            double C = atomicAdd(&g_acc[0], 0.0);
            double P = atomicAdd(&g_acc[1], 0.0);
            double denom = 32.0 * 510.0 * 510.0;
            out[0] = (float)(0.4 * (C / denom) + 0.2 * bc + (1.0 - 0.4 - 0.2) * (P / denom));
            g_acc[0] = 0.0; g_acc[1] = 0.0;
        }
        if (tid < NBATCH * 4) g_bc4[tid] = 0.0;
        __threadfence();
        __syncthreads();
        if (tid == 0) g_count = 0u;
    }
}

extern "C" void kernel_launch(void* const* d_in, const int* in_sizes, int n_in,
                              void* d_out, int out_size) {
    const float* gen = (const float*)d_in[0];
    const float* pn  = (const float*)d_in[1];
    float* out = (float*)d_out;
    dim3 grid(16, 8, NBATCH);   // 16 x 8 x 32 = 4096 blocks
    pil_kernel<<<grid, 256>>>(gen, pn, out);
}